// round 9
// baseline (speedup 1.0000x reference)
#include <cuda_runtime.h>
#include <math.h>

// Problem constants
#define BB   8
#define CCH  64
#define HH   112
#define WW   112
#define MID  256
#define NTAP 25

// Tiling
#define TW   16
#define TH   16
#define PW   24          // TW + 8 halo
#define PH   24          // TH + 8 halo
#define CHK  8           // channel chunk
#define NCHK (CCH / CHK) // 8
#define NT   64          // threads per CTA (each owns TWO pixel-pairs: rows pr, pr+8)

#define WROW 28          // weight row: 25 outputs + 3 pad floats -> 112 B, 16B aligned
#define NACC 13          // 13 f32x2 accumulators cover outputs 0..25 (o>=25 is pad)

// Effective weights, COMPACT layout: [c][tap][o(0..24) pad to 28 floats]
__device__ __align__(16) float g_w2o[CCH * NTAP * WROW];
__device__ float g_beff[NTAP];

__device__ __forceinline__ unsigned long long ffma2(unsigned long long a,
                                                    unsigned long long x,
                                                    unsigned long long c) {
    unsigned long long d;
    asm("fma.rn.f32x2 %0, %1, %2, %3;" : "=l"(d) : "l"(a), "l"(x), "l"(c));
    return d;
}

__device__ __forceinline__ void unpack2(unsigned long long v, float& a, float& b) {
    asm("mov.b64 {%0,%1}, %2;" : "=f"(a), "=f"(b) : "l"(v));
}

__device__ __forceinline__ unsigned long long pack2(float a, float b) {
    unsigned long long v;
    asm("mov.b64 %0, {%1,%2};" : "=l"(v) : "f"(a), "f"(b));
    return v;
}

__device__ __forceinline__ unsigned long long pack_dup(float a) {
    unsigned long long v;
    asm("mov.b64 %0, {%1,%1};" : "=l"(v) : "f"(a));
    return v;
}

// Compose conv1 (5x5 dil-2) and conv2 (1x1) into one effective 25-output conv.
__global__ void k_precompute(const float* __restrict__ w1, const float* __restrict__ b1,
                             const float* __restrict__ w2, const float* __restrict__ b2) {
    int idx = blockIdx.x * blockDim.x + threadIdx.x;
    if (idx < CCH * NTAP * NTAP) {
        int o = idx % NTAP;
        int t = (idx / NTAP) % NTAP;
        int c = idx / (NTAP * NTAP);
        float s = 0.f;
        #pragma unroll 4
        for (int m = 0; m < MID; ++m)
            s = fmaf(w2[o * MID + m], w1[(m * CCH + c) * NTAP + t], s);
        g_w2o[(c * NTAP + t) * WROW + o] = s;
    }
    if (idx < CCH * NTAP) {   // zero the 3 pad floats of each row
        int base = idx * WROW;
        g_w2o[base + 25] = 0.f;
        g_w2o[base + 26] = 0.f;
        g_w2o[base + 27] = 0.f;
    }
    if (idx < NTAP) {
        float s = b2[idx];
        for (int m = 0; m < MID; ++m) s = fmaf(w2[idx * MID + m], b1[m], s);
        g_beff[idx] = s;
    }
}

__device__ __forceinline__ void load_patch(float* sP, const float* __restrict__ xb,
                                           int cc, int gy0, int gx0, int tid) {
    #pragma unroll 1
    for (int i = tid; i < CHK * PH * PW; i += NT) {
        int c   = i / (PH * PW);
        int rem = i - c * (PH * PW);
        int r   = rem / PW;
        int col = rem - r * PW;
        int gr = gy0 - 4 + r;
        int gc = gx0 - 4 + col;
        float v = 0.f;
        if (gr >= 0 && gr < HH && gc >= 0 && gc < WW)
            v = xb[((cc * CHK + c) * HH + gr) * WW + gc];
        sP[i] = v;
    }
}

__global__ __launch_bounds__(NT, 4)
void k_main(const float* __restrict__ x, float* __restrict__ out) {
    extern __shared__ char sraw[];
    float* sWf = (float*)sraw;                                 // CHK*25*28 floats (22400 B)
    float* sP  = (float*)(sraw + CHK * NTAP * WROW * 4);       // CHK*PH*PW floats (18432 B)

    const int b   = blockIdx.z;
    const int gx0 = blockIdx.x * TW;
    const int gy0 = blockIdx.y * TH;
    const int tid = threadIdx.x;
    const int pr  = tid >> 3;      // 0..7: pair A at row pr, pair B at row pr+8
    const int pc  = tid & 7;       // pixel-pair column (px = 2*pc, 2*pc+1)

    const float* xb = x + (size_t)b * CCH * HH * WW;

    // Accumulators: A/B = row-slot, 0/1 = pixel within pair.
    // Each u64 holds logits (2j, 2j+1) for that pixel.
    unsigned long long accA0[NACC], accA1[NACC], accB0[NACC], accB1[NACC];
    #pragma unroll
    for (int j = 0; j < NACC; ++j) {
        accA0[j] = 0ull; accA1[j] = 0ull; accB0[j] = 0ull; accB1[j] = 0ull;
    }

    // ---------------- Phase 1: 25 logits per pixel ----------------
    #pragma unroll 1
    for (int cc = 0; cc < NCHK; ++cc) {
        load_patch(sP, xb, cc, gy0, gx0, tid);
        {   // stage compact weights for this channel chunk: 22400 B
            const float4* wg = (const float4*)(g_w2o + (size_t)cc * (CHK * NTAP * WROW));
            float4* ws = (float4*)sWf;
            #pragma unroll 1
            for (int i = tid; i < CHK * NTAP * WROW / 4; i += NT) ws[i] = wg[i];
        }
        __syncthreads();

        const float* pA = sP + pr * PW + 2 * pc;
        const float* pB = sP + (pr + 8) * PW + 2 * pc;
        #pragma unroll 1
        for (int c = 0; c < CHK; ++c) {
            const float* wc  = sWf + c * (NTAP * WROW);
            const float* pcA = pA + c * (PH * PW);
            const float* pcB = pB + c * (PH * PW);
            #pragma unroll
            for (int t = 0; t < NTAP; ++t) {
                const int dy = (t / 5) * 2, dx = (t % 5) * 2;
                unsigned long long xvA =
                    *(const unsigned long long*)(pcA + dy * PW + dx);
                unsigned long long xvB =
                    *(const unsigned long long*)(pcB + dy * PW + dx);
                float a0, a1, b0, b1;
                unpack2(xvA, a0, a1);
                unpack2(xvB, b0, b1);
                unsigned long long dA0 = pack_dup(a0), dA1 = pack_dup(a1);
                unsigned long long dB0 = pack_dup(b0), dB1 = pack_dup(b1);
                const ulonglong2* wp = (const ulonglong2*)(wc + t * WROW);
                #pragma unroll
                for (int h = 0; h < 7; ++h) {
                    ulonglong2 wv = wp[h];           // LDS.128, warp-broadcast
                    accA0[2*h] = ffma2(wv.x, dA0, accA0[2*h]);
                    accA1[2*h] = ffma2(wv.x, dA1, accA1[2*h]);
                    accB0[2*h] = ffma2(wv.x, dB0, accB0[2*h]);
                    accB1[2*h] = ffma2(wv.x, dB1, accB1[2*h]);
                    if (2*h + 1 < NACC) {
                        accA0[2*h+1] = ffma2(wv.y, dA0, accA0[2*h+1]);
                        accA1[2*h+1] = ffma2(wv.y, dA1, accA1[2*h+1]);
                        accB0[2*h+1] = ffma2(wv.y, dB0, accB0[2*h+1]);
                        accB1[2*h+1] = ffma2(wv.y, dB1, accB1[2*h+1]);
                    }
                }
            }
        }
        __syncthreads();
    }

    // ---------------- Softmax over the 25 taps (per pixel) ----------------
    // Done per pair-slot to cap live registers. ak*[t] = (k_px0, k_px1) packed.
    unsigned long long akA[NTAP], akB[NTAP];
    {
        float p0[26], p1[26];
        #pragma unroll
        for (int j = 0; j < NACC; ++j) {
            unpack2(accA0[j], p0[2*j], p0[2*j+1]);
            unpack2(accA1[j], p1[2*j], p1[2*j+1]);
        }
        #pragma unroll
        for (int o = 0; o < NTAP; ++o) { float be = g_beff[o]; p0[o] += be; p1[o] += be; }
        float m0 = p0[0], m1 = p1[0];
        #pragma unroll
        for (int o = 1; o < NTAP; ++o) { m0 = fmaxf(m0, p0[o]); m1 = fmaxf(m1, p1[o]); }
        float s0 = 0.f, s1 = 0.f;
        #pragma unroll
        for (int o = 0; o < NTAP; ++o) {
            p0[o] = __expf(p0[o] - m0); p1[o] = __expf(p1[o] - m1);
            s0 += p0[o]; s1 += p1[o];
        }
        float r0 = 1.f / s0, r1 = 1.f / s1;
        #pragma unroll
        for (int t = 0; t < NTAP; ++t) akA[t] = pack2(p0[t] * r0, p1[t] * r1);
    }
    {
        float p0[26], p1[26];
        #pragma unroll
        for (int j = 0; j < NACC; ++j) {
            unpack2(accB0[j], p0[2*j], p0[2*j+1]);
            unpack2(accB1[j], p1[2*j], p1[2*j+1]);
        }
        #pragma unroll
        for (int o = 0; o < NTAP; ++o) { float be = g_beff[o]; p0[o] += be; p1[o] += be; }
        float m0 = p0[0], m1 = p1[0];
        #pragma unroll
        for (int o = 1; o < NTAP; ++o) { m0 = fmaxf(m0, p0[o]); m1 = fmaxf(m1, p1[o]); }
        float s0 = 0.f, s1 = 0.f;
        #pragma unroll
        for (int o = 0; o < NTAP; ++o) {
            p0[o] = __expf(p0[o] - m0); p1[o] = __expf(p1[o] - m1);
            s0 += p0[o]; s1 += p1[o];
        }
        float r0 = 1.f / s0, r1 = 1.f / s1;
        #pragma unroll
        for (int t = 0; t < NTAP; ++t) akB[t] = pack2(p0[t] * r0, p1[t] * r1);
    }

    // ---------------- Phase 2: attention-weighted neighborhood sum ----------------
    #pragma unroll 1
    for (int cc = 0; cc < NCHK; ++cc) {
        load_patch(sP, xb, cc, gy0, gx0, tid);
        __syncthreads();

        const float* pA = sP + pr * PW + 2 * pc;
        const float* pB = sP + (pr + 8) * PW + 2 * pc;
        #pragma unroll 1
        for (int c = 0; c < CHK; ++c) {
            const float* pcA = pA + c * (PH * PW);
            const float* pcB = pB + c * (PH * PW);
            // interleaved chains to hide FFMA2 latency
            unsigned long long ovA0 = 0ull, ovA1 = 0ull, ovB0 = 0ull, ovB1 = 0ull;
            #pragma unroll
            for (int t = 0; t < NTAP - 1; t += 2) {
                const int dy0 = (t / 5) * 2,       dx0 = (t % 5) * 2;
                const int dy1 = ((t + 1) / 5) * 2, dx1 = ((t + 1) % 5) * 2;
                unsigned long long xA0 = *(const unsigned long long*)(pcA + dy0 * PW + dx0);
                unsigned long long xA1 = *(const unsigned long long*)(pcA + dy1 * PW + dx1);
                unsigned long long xB0 = *(const unsigned long long*)(pcB + dy0 * PW + dx0);
                unsigned long long xB1 = *(const unsigned long long*)(pcB + dy1 * PW + dx1);
                ovA0 = ffma2(akA[t],     xA0, ovA0);
                ovA1 = ffma2(akA[t + 1], xA1, ovA1);
                ovB0 = ffma2(akB[t],     xB0, ovB0);
                ovB1 = ffma2(akB[t + 1], xB1, ovB1);
            }
            {   // tap 24
                unsigned long long xA = *(const unsigned long long*)(pcA + 8 * PW + 8);
                unsigned long long xB = *(const unsigned long long*)(pcB + 8 * PW + 8);
                ovA0 = ffma2(akA[24], xA, ovA0);
                ovB0 = ffma2(akB[24], xB, ovB0);
            }
            float u0, u1, v0, v1;
            unpack2(ovA0, u0, u1); unpack2(ovA1, v0, v1);
            float2 oA = make_float2(u0 + v0, u1 + v1);
            unpack2(ovB0, u0, u1); unpack2(ovB1, v0, v1);
            float2 oB = make_float2(u0 + v0, u1 + v1);
            size_t chbase = ((size_t)b * CCH + cc * CHK + c) * HH;
            *(float2*)&out[(chbase + gy0 + pr) * WW + gx0 + 2 * pc]     = oA;
            *(float2*)&out[(chbase + gy0 + pr + 8) * WW + gx0 + 2 * pc] = oB;
        }
        __syncthreads();
    }
}

extern "C" void kernel_launch(void* const* d_in, const int* in_sizes, int n_in,
                              void* d_out, int out_size) {
    const float* x  = (const float*)d_in[0];
    const float* w1 = (const float*)d_in[1];
    const float* b1 = (const float*)d_in[2];
    const float* w2 = (const float*)d_in[3];
    const float* b2 = (const float*)d_in[4];
    float* out = (float*)d_out;

    // Fold conv1 + conv2 into effective 25-output conv weights/bias.
    k_precompute<<<(CCH * NTAP * NTAP + 255) / 256, 256>>>(w1, b1, w2, b2);

    const int smem_bytes = CHK * NTAP * WROW * 4 + CHK * PH * PW * 4; // 22400 + 18432 = 40832
    cudaFuncSetAttribute(k_main, cudaFuncAttributeMaxDynamicSharedMemorySize, smem_bytes);

    dim3 grid(WW / TW, HH / TH, BB);   // 7 x 7 x 8 = 392 CTAs
    k_main<<<grid, NT, smem_bytes>>>(x, out);
}

// round 14
// speedup vs baseline: 1.4390x; 1.4390x over previous
#include <cuda_runtime.h>
#include <math.h>

// Problem constants
#define BB   8
#define CCH  64
#define HH   112
#define WW   112
#define MID  256
#define NTAP 25
#define NOUT 32          // padded outputs (25 real + 7 zero)

// Tiling
#define TW   16
#define TH   16
#define PW   24          // TW + 8 halo
#define PH   24          // TH + 8 halo
#define CHK  8           // channel chunk
#define NCHK (CCH / CHK) // 8
#define NT   256         // 8 warps; warp w covers tile rows {2w, 2w+1}

// Effective weights: [c][tap][o 0..31], pads zero. 64*25*32 floats.
__device__ __align__(16) float g_w2o[CCH * NTAP * NOUT];
__device__ float g_beff[NTAP];

__device__ __forceinline__ unsigned long long ffma2(unsigned long long a,
                                                    unsigned long long x,
                                                    unsigned long long c) {
    unsigned long long d;
    asm("fma.rn.f32x2 %0, %1, %2, %3;" : "=l"(d) : "l"(a), "l"(x), "l"(c));
    return d;
}
__device__ __forceinline__ void unpack2(unsigned long long v, float& a, float& b) {
    asm("mov.b64 {%0,%1}, %2;" : "=f"(a), "=f"(b) : "l"(v));
}
__device__ __forceinline__ unsigned long long pack2(float a, float b) {
    unsigned long long v;
    asm("mov.b64 %0, {%1,%2};" : "=l"(v) : "f"(a), "f"(b));
    return v;
}
__device__ __forceinline__ unsigned long long pack_dup(float a) {
    unsigned long long v;
    asm("mov.b64 %0, {%1,%1};" : "=l"(v) : "f"(a));
    return v;
}

// Compose conv1 (5x5 dil-2) and conv2 (1x1) into one effective 25-output conv.
__global__ void k_precompute(const float* __restrict__ w1, const float* __restrict__ b1,
                             const float* __restrict__ w2, const float* __restrict__ b2) {
    int idx = blockIdx.x * blockDim.x + threadIdx.x;
    if (idx < CCH * NTAP * NOUT) {
        int o = idx % NOUT;
        int t = (idx / NOUT) % NTAP;
        int c = idx / (NOUT * NTAP);
        float s = 0.f;
        if (o < NTAP) {
            #pragma unroll 4
            for (int m = 0; m < MID; ++m)
                s = fmaf(w2[o * MID + m], w1[(m * CCH + c) * NTAP + t], s);
        }
        g_w2o[(c * NTAP + t) * NOUT + o] = s;
    }
    if (idx < NTAP) {
        float s = b2[idx];
        for (int m = 0; m < MID; ++m) s = fmaf(w2[idx * MID + m], b1[m], s);
        g_beff[idx] = s;
    }
}

__device__ __forceinline__ void load_patch(float* sP, const float* __restrict__ xb,
                                           int cc, int gy0, int gx0, int tid) {
    #pragma unroll 1
    for (int i = tid; i < CHK * PH * PW; i += NT) {
        int c   = i / (PH * PW);
        int rem = i - c * (PH * PW);
        int r   = rem / PW;
        int col = rem - r * PW;
        int gr = gy0 - 4 + r;
        int gc = gx0 - 4 + col;
        float v = 0.f;
        if (gr >= 0 && gr < HH && gc >= 0 && gc < WW)
            v = xb[((cc * CHK + c) * HH + gr) * WW + gc];
        sP[i] = v;
    }
}

// smem layout: region A (25600 B) = weight stage (phase 1) UNION kS[25][128] u64
//              patch at +25600 (18432 B). Total 44032 B.
#define SM_WBYTES (CHK * NTAP * NOUT * 4)     // 25600
#define SM_TOTAL  (SM_WBYTES + CHK * PH * PW * 4)

__global__ __launch_bounds__(NT, 3)
void k_main(const float* __restrict__ x, float* __restrict__ out) {
    extern __shared__ char sraw[];
    float* sW = (float*)sraw;                              // phase-1 weight stage
    unsigned long long* kS = (unsigned long long*)sraw;    // phase-2 attn weights (alias)
    float* sP = (float*)(sraw + SM_WBYTES);                // patch

    const int b   = blockIdx.z;
    const int gx0 = blockIdx.x * TW;
    const int gy0 = blockIdx.y * TH;
    const int tid = threadIdx.x;
    const int wid = tid >> 5;
    const int ln  = tid & 31;
    const int og  = ln >> 2;       // output group 0..7 (outs 4*og..4*og+3)
    const int pg  = ln & 3;        // pixel group: 4 pairs each

    // lane's pixel geometry: warp rows {2*wid, 2*wid+1}
    const int xrow  = 2 * wid + (pg >> 1);   // tile row of this lane's pairs
    const int xcolb = (pg & 1) * 8;          // starting col (floats) of its 4 pairs

    const float* xb = x + (size_t)b * CCH * HH * WW;

    // acc[i][j]: pair i (cols xcolb+2i), out 4*og+j ; u64 = (px0, px1)
    unsigned long long acc[4][4];
    #pragma unroll
    for (int i = 0; i < 4; ++i)
        #pragma unroll
        for (int j = 0; j < 4; ++j) acc[i][j] = 0ull;

    // ---------------- Phase 1: logits ----------------
    #pragma unroll 1
    for (int cc = 0; cc < NCHK; ++cc) {
        load_patch(sP, xb, cc, gy0, gx0, tid);
        {   // stage weights for chunk: 6400 floats
            const float4* wg = (const float4*)(g_w2o + (size_t)cc * (CHK * NTAP * NOUT));
            float4* ws = (float4*)sW;
            #pragma unroll 1
            for (int i = tid; i < CHK * NTAP * NOUT / 4; i += NT) ws[i] = wg[i];
        }
        __syncthreads();

        #pragma unroll 1
        for (int c = 0; c < CHK; ++c) {
            const float* pc0 = sP + c * (PH * PW) + xrow * PW + xcolb;
            const float4* wc = (const float4*)(sW + c * (NTAP * NOUT));
            #pragma unroll
            for (int t = 0; t < NTAP; ++t) {
                const int dy = (t / 5) * 2, dx = (t % 5) * 2;
                const float* px = pc0 + dy * PW + dx;
                unsigned long long x0 = *(const unsigned long long*)(px + 0);
                unsigned long long x1 = *(const unsigned long long*)(px + 2);
                unsigned long long x2 = *(const unsigned long long*)(px + 4);
                unsigned long long x3 = *(const unsigned long long*)(px + 6);
                float4 wv = wc[t * (NOUT / 4) + og];          // 1 LDS.128, coalesced
                unsigned long long d0 = pack_dup(wv.x);
                unsigned long long d1 = pack_dup(wv.y);
                unsigned long long d2 = pack_dup(wv.z);
                unsigned long long d3 = pack_dup(wv.w);
                acc[0][0] = ffma2(d0, x0, acc[0][0]);
                acc[1][0] = ffma2(d0, x1, acc[1][0]);
                acc[2][0] = ffma2(d0, x2, acc[2][0]);
                acc[3][0] = ffma2(d0, x3, acc[3][0]);
                acc[0][1] = ffma2(d1, x0, acc[0][1]);
                acc[1][1] = ffma2(d1, x1, acc[1][1]);
                acc[2][1] = ffma2(d1, x2, acc[2][1]);
                acc[3][1] = ffma2(d1, x3, acc[3][1]);
                acc[0][2] = ffma2(d2, x0, acc[0][2]);
                acc[1][2] = ffma2(d2, x1, acc[1][2]);
                acc[2][2] = ffma2(d2, x2, acc[2][2]);
                acc[3][2] = ffma2(d2, x3, acc[3][2]);
                acc[0][3] = ffma2(d3, x0, acc[0][3]);
                acc[1][3] = ffma2(d3, x1, acc[1][3]);
                acc[2][3] = ffma2(d3, x2, acc[2][3]);
                acc[3][3] = ffma2(d3, x3, acc[3][3]);
            }
        }
        __syncthreads();
    }

    // ---------------- Softmax across og-lanes (bfly over lane bits 2..4) ----------------
    // Lane holds outs {4og..4og+3}; real outs are o<25: og<6 all 4, og==6 only j==0.
    const int nreal = (og < 6) ? 4 : (og == 6 ? 1 : 0);
    #pragma unroll 1
    for (int i = 0; i < 4; ++i) {
        float l0[4], l1[4];
        #pragma unroll
        for (int j = 0; j < 4; ++j) {
            float a, bv;
            unpack2(acc[i][j], a, bv);
            int o = 4 * og + j;
            if (j < nreal) {
                float be = g_beff[o];
                l0[j] = a + be; l1[j] = bv + be;
            } else {
                l0[j] = -1e30f; l1[j] = -1e30f;
            }
        }
        float m0 = fmaxf(fmaxf(l0[0], l0[1]), fmaxf(l0[2], l0[3]));
        float m1 = fmaxf(fmaxf(l1[0], l1[1]), fmaxf(l1[2], l1[3]));
        #pragma unroll
        for (int d = 4; d <= 16; d <<= 1) {
            m0 = fmaxf(m0, __shfl_xor_sync(0xffffffffu, m0, d));
            m1 = fmaxf(m1, __shfl_xor_sync(0xffffffffu, m1, d));
        }
        float e0[4], e1[4];
        float s0 = 0.f, s1 = 0.f;
        #pragma unroll
        for (int j = 0; j < 4; ++j) {
            e0[j] = (j < nreal) ? __expf(l0[j] - m0) : 0.f;
            e1[j] = (j < nreal) ? __expf(l1[j] - m1) : 0.f;
            s0 += e0[j]; s1 += e1[j];
        }
        #pragma unroll
        for (int d = 4; d <= 16; d <<= 1) {
            s0 += __shfl_xor_sync(0xffffffffu, s0, d);
            s1 += __shfl_xor_sync(0xffffffffu, s1, d);
        }
        float r0 = 1.f / s0, r1 = 1.f / s1;
        // write attn weights to kS[o][pairG]
        int pairG = xrow * 8 + (xcolb >> 1) + i;
        #pragma unroll
        for (int j = 0; j < 4; ++j) {
            if (j < nreal)
                kS[(4 * og + j) * 128 + pairG] = pack2(e0[j] * r0, e1[j] * r1);
        }
    }
    __syncthreads();

    // ---------------- Phase 2: attention-weighted neighborhood sum ----------------
    // remap: thread -> (pairG = tid & 127, channel half = tid >> 7)
    const int pairG2 = tid & 127;
    const int chalf  = tid >> 7;           // 0/1 -> channels {0..3} or {4..7} of chunk
    const int prow   = pairG2 >> 3;
    const int pcol   = (pairG2 & 7) * 2;

    #pragma unroll 1
    for (int cc = 0; cc < NCHK; ++cc) {
        load_patch(sP, xb, cc, gy0, gx0, tid);
        __syncthreads();

        unsigned long long accO[4];
        #pragma unroll
        for (int q = 0; q < 4; ++q) accO[q] = 0ull;

        const float* pb = sP + (chalf * 4) * (PH * PW) + prow * PW + pcol;
        #pragma unroll
        for (int t = 0; t < NTAP; ++t) {
            const int dy = (t / 5) * 2, dx = (t % 5) * 2;
            unsigned long long ak = kS[t * 128 + pairG2];
            const float* px = pb + dy * PW + dx;
            #pragma unroll
            for (int q = 0; q < 4; ++q) {
                unsigned long long xv =
                    *(const unsigned long long*)(px + q * (PH * PW));
                accO[q] = ffma2(ak, xv, accO[q]);
            }
        }

        #pragma unroll
        for (int q = 0; q < 4; ++q) {
            float a, bv;
            unpack2(accO[q], a, bv);
            int ch = cc * CHK + chalf * 4 + q;
            *(float2*)&out[(((size_t)b * CCH + ch) * HH + (gy0 + prow)) * WW
                           + gx0 + pcol] = make_float2(a, bv);
        }
        __syncthreads();
    }
}

extern "C" void kernel_launch(void* const* d_in, const int* in_sizes, int n_in,
                              void* d_out, int out_size) {
    const float* x  = (const float*)d_in[0];
    const float* w1 = (const float*)d_in[1];
    const float* b1 = (const float*)d_in[2];
    const float* w2 = (const float*)d_in[3];
    const float* b2 = (const float*)d_in[4];
    float* out = (float*)d_out;

    k_precompute<<<(CCH * NTAP * NOUT + 255) / 256, 256>>>(w1, b1, w2, b2);

    cudaFuncSetAttribute(k_main, cudaFuncAttributeMaxDynamicSharedMemorySize, SM_TOTAL);

    dim3 grid(WW / TW, HH / TH, BB);   // 7 x 7 x 8 = 392 CTAs
    k_main<<<grid, NT, SM_TOTAL>>>(x, out);
}

// round 15
// speedup vs baseline: 1.4480x; 1.0062x over previous
#include <cuda_runtime.h>
#include <math.h>

// Problem constants
#define BB   8
#define CCH  64
#define HH   112
#define WW   112
#define MID  256
#define NTAP 25
#define NOUT 32          // padded outputs (25 real + 7 zero)

// Tiling
#define TW   16
#define TH   16
#define PW   24          // logical patch width: TW + 8 halo
#define PWP  28          // PADDED patch pitch (112B rows -> conflict-free pg offsets)
#define PH   24          // TH + 8 halo
#define CHK  8           // channel chunk
#define NCHK (CCH / CHK) // 8
#define NT   256         // 8 warps; warp w covers tile rows {2w, 2w+1}

// Effective weights: [c][tap][o 0..31], pads zero. 64*25*32 floats.
__device__ __align__(16) float g_w2o[CCH * NTAP * NOUT];
__device__ float g_beff[NTAP];

__device__ __forceinline__ unsigned long long ffma2(unsigned long long a,
                                                    unsigned long long x,
                                                    unsigned long long c) {
    unsigned long long d;
    asm("fma.rn.f32x2 %0, %1, %2, %3;" : "=l"(d) : "l"(a), "l"(x), "l"(c));
    return d;
}
__device__ __forceinline__ void unpack2(unsigned long long v, float& a, float& b) {
    asm("mov.b64 {%0,%1}, %2;" : "=f"(a), "=f"(b) : "l"(v));
}
__device__ __forceinline__ unsigned long long pack2(float a, float b) {
    unsigned long long v;
    asm("mov.b64 %0, {%1,%2};" : "=l"(v) : "f"(a), "f"(b));
    return v;
}
__device__ __forceinline__ unsigned long long pack_dup(float a) {
    unsigned long long v;
    asm("mov.b64 %0, {%1,%1};" : "=l"(v) : "f"(a));
    return v;
}

// Compose conv1 (5x5 dil-2) and conv2 (1x1) into one effective 25-output conv.
__global__ void k_precompute(const float* __restrict__ w1, const float* __restrict__ b1,
                             const float* __restrict__ w2, const float* __restrict__ b2) {
    int idx = blockIdx.x * blockDim.x + threadIdx.x;
    if (idx < CCH * NTAP * NOUT) {
        int o = idx % NOUT;
        int t = (idx / NOUT) % NTAP;
        int c = idx / (NOUT * NTAP);
        float s = 0.f;
        if (o < NTAP) {
            #pragma unroll 4
            for (int m = 0; m < MID; ++m)
                s = fmaf(w2[o * MID + m], w1[(m * CCH + c) * NTAP + t], s);
        }
        g_w2o[(c * NTAP + t) * NOUT + o] = s;
    }
    if (idx < NTAP) {
        float s = b2[idx];
        for (int m = 0; m < MID; ++m) s = fmaf(w2[idx * MID + m], b1[m], s);
        g_beff[idx] = s;
    }
}

// Load CHK channels of the 24x24 logical patch into a PWP-pitched smem buffer.
// Padding columns 24..27 are never read, so they stay unwritten.
__device__ __forceinline__ void load_patch(float* sP, const float* __restrict__ xb,
                                           int cc, int gy0, int gx0, int tid) {
    #pragma unroll 1
    for (int i = tid; i < CHK * PH * PW; i += NT) {
        int c   = i / (PH * PW);
        int rem = i - c * (PH * PW);
        int r   = rem / PW;
        int col = rem - r * PW;
        int gr = gy0 - 4 + r;
        int gc = gx0 - 4 + col;
        float v = 0.f;
        if (gr >= 0 && gr < HH && gc >= 0 && gc < WW)
            v = xb[((cc * CHK + c) * HH + gr) * WW + gc];
        sP[c * (PH * PWP) + r * PWP + col] = v;
    }
}

// smem layout: region A (25600 B) = weight stage (phase 1) UNION kS[25][128] u64
//              patch at +25600: CHK*PH*PWP floats = 21504 B. Total 47104 B.
#define SM_WBYTES (CHK * NTAP * NOUT * 4)     // 25600
#define SM_TOTAL  (SM_WBYTES + CHK * PH * PWP * 4)

__global__ __launch_bounds__(NT, 3)
void k_main(const float* __restrict__ x, float* __restrict__ out) {
    extern __shared__ char sraw[];
    float* sW = (float*)sraw;                              // phase-1 weight stage
    unsigned long long* kS = (unsigned long long*)sraw;    // phase-2 attn weights (alias)
    float* sP = (float*)(sraw + SM_WBYTES);                // patch (PWP pitch)

    const int b   = blockIdx.z;
    const int gx0 = blockIdx.x * TW;
    const int gy0 = blockIdx.y * TH;
    const int tid = threadIdx.x;
    const int wid = tid >> 5;
    const int ln  = tid & 31;
    const int og  = ln >> 2;       // output group 0..7 (outs 4*og..4*og+3)
    const int pg  = ln & 3;        // pixel group: 4 pairs each

    // lane's pixel geometry: warp rows {2*wid, 2*wid+1}
    const int xrow  = 2 * wid + (pg >> 1);   // tile row of this lane's pairs
    const int xcolb = (pg & 1) * 8;          // starting col (floats) of its 4 pairs

    const float* xb = x + (size_t)b * CCH * HH * WW;

    // acc[i][j]: pair i (cols xcolb+2i), out 4*og+j ; u64 = (px0, px1)
    unsigned long long acc[4][4];
    #pragma unroll
    for (int i = 0; i < 4; ++i)
        #pragma unroll
        for (int j = 0; j < 4; ++j) acc[i][j] = 0ull;

    // ---------------- Phase 1: logits (row-register-cached) ----------------
    #pragma unroll 1
    for (int cc = 0; cc < NCHK; ++cc) {
        load_patch(sP, xb, cc, gy0, gx0, tid);
        {   // stage weights for chunk: 6400 floats
            const float4* wg = (const float4*)(g_w2o + (size_t)cc * (CHK * NTAP * NOUT));
            float4* ws = (float4*)sW;
            #pragma unroll 1
            for (int i = tid; i < CHK * NTAP * NOUT / 4; i += NT) ws[i] = wg[i];
        }
        __syncthreads();

        #pragma unroll 1
        for (int c = 0; c < CHK; ++c) {
            const float* base = sP + c * (PH * PWP) + xrow * PWP + xcolb;
            const float4* wc  = (const float4*)(sW + c * (NTAP * NOUT));
            #pragma unroll
            for (int dy = 0; dy < 5; ++dy) {
                // Load the 16-float row segment once; all 5 taps of this row use it.
                const float4* rp = (const float4*)(base + 2 * dy * PWP);
                float4 r0 = rp[0], r1 = rp[1], r2 = rp[2], r3 = rp[3];
                unsigned long long xr[8];
                xr[0] = pack2(r0.x, r0.y); xr[1] = pack2(r0.z, r0.w);
                xr[2] = pack2(r1.x, r1.y); xr[3] = pack2(r1.z, r1.w);
                xr[4] = pack2(r2.x, r2.y); xr[5] = pack2(r2.z, r2.w);
                xr[6] = pack2(r3.x, r3.y); xr[7] = pack2(r3.z, r3.w);
                #pragma unroll
                for (int tx = 0; tx < 5; ++tx) {
                    float4 wv = wc[(dy * 5 + tx) * (NOUT / 4) + og];  // 1 LDS.128
                    unsigned long long d0 = pack_dup(wv.x);
                    unsigned long long d1 = pack_dup(wv.y);
                    unsigned long long d2 = pack_dup(wv.z);
                    unsigned long long d3 = pack_dup(wv.w);
                    // pair i reads xr[tx + i]  (dx = 2*tx, cols xcolb+2i+2tx)
                    acc[0][0] = ffma2(d0, xr[tx],     acc[0][0]);
                    acc[1][0] = ffma2(d0, xr[tx + 1], acc[1][0]);
                    acc[2][0] = ffma2(d0, xr[tx + 2], acc[2][0]);
                    acc[3][0] = ffma2(d0, xr[tx + 3], acc[3][0]);
                    acc[0][1] = ffma2(d1, xr[tx],     acc[0][1]);
                    acc[1][1] = ffma2(d1, xr[tx + 1], acc[1][1]);
                    acc[2][1] = ffma2(d1, xr[tx + 2], acc[2][1]);
                    acc[3][1] = ffma2(d1, xr[tx + 3], acc[3][1]);
                    acc[0][2] = ffma2(d2, xr[tx],     acc[0][2]);
                    acc[1][2] = ffma2(d2, xr[tx + 1], acc[1][2]);
                    acc[2][2] = ffma2(d2, xr[tx + 2], acc[2][2]);
                    acc[3][2] = ffma2(d2, xr[tx + 3], acc[3][2]);
                    acc[0][3] = ffma2(d3, xr[tx],     acc[0][3]);
                    acc[1][3] = ffma2(d3, xr[tx + 1], acc[1][3]);
                    acc[2][3] = ffma2(d3, xr[tx + 2], acc[2][3]);
                    acc[3][3] = ffma2(d3, xr[tx + 3], acc[3][3]);
                }
            }
        }
        __syncthreads();
    }

    // ---------------- Softmax across og-lanes (bfly over lane bits 2..4) ----------------
    // Lane holds outs {4og..4og+3}; real outs are o<25: og<6 all 4, og==6 only j==0.
    const int nreal = (og < 6) ? 4 : (og == 6 ? 1 : 0);
    #pragma unroll 1
    for (int i = 0; i < 4; ++i) {
        float l0[4], l1[4];
        #pragma unroll
        for (int j = 0; j < 4; ++j) {
            float a, bv;
            unpack2(acc[i][j], a, bv);
            int o = 4 * og + j;
            if (j < nreal) {
                float be = g_beff[o];
                l0[j] = a + be; l1[j] = bv + be;
            } else {
                l0[j] = -1e30f; l1[j] = -1e30f;
            }
        }
        float m0 = fmaxf(fmaxf(l0[0], l0[1]), fmaxf(l0[2], l0[3]));
        float m1 = fmaxf(fmaxf(l1[0], l1[1]), fmaxf(l1[2], l1[3]));
        #pragma unroll
        for (int d = 4; d <= 16; d <<= 1) {
            m0 = fmaxf(m0, __shfl_xor_sync(0xffffffffu, m0, d));
            m1 = fmaxf(m1, __shfl_xor_sync(0xffffffffu, m1, d));
        }
        float e0[4], e1[4];
        float s0 = 0.f, s1 = 0.f;
        #pragma unroll
        for (int j = 0; j < 4; ++j) {
            e0[j] = (j < nreal) ? __expf(l0[j] - m0) : 0.f;
            e1[j] = (j < nreal) ? __expf(l1[j] - m1) : 0.f;
            s0 += e0[j]; s1 += e1[j];
        }
        #pragma unroll
        for (int d = 4; d <= 16; d <<= 1) {
            s0 += __shfl_xor_sync(0xffffffffu, s0, d);
            s1 += __shfl_xor_sync(0xffffffffu, s1, d);
        }
        float r0 = 1.f / s0, r1 = 1.f / s1;
        // write attn weights to kS[o][pairG]
        int pairG = xrow * 8 + (xcolb >> 1) + i;
        #pragma unroll
        for (int j = 0; j < 4; ++j) {
            if (j < nreal)
                kS[(4 * og + j) * 128 + pairG] = pack2(e0[j] * r0, e1[j] * r1);
        }
    }
    __syncthreads();

    // ---------------- Phase 2: attention-weighted neighborhood sum ----------------
    // remap: thread -> (pairG = tid & 127, channel half = tid >> 7)
    const int pairG2 = tid & 127;
    const int chalf  = tid >> 7;           // 0/1 -> channels {0..3} or {4..7} of chunk
    const int prow   = pairG2 >> 3;
    const int pcol   = (pairG2 & 7) * 2;

    #pragma unroll 1
    for (int cc = 0; cc < NCHK; ++cc) {
        load_patch(sP, xb, cc, gy0, gx0, tid);
        __syncthreads();

        unsigned long long accO[4];
        #pragma unroll
        for (int q = 0; q < 4; ++q) accO[q] = 0ull;

        const float* pb = sP + (chalf * 4) * (PH * PWP) + prow * PWP + pcol;
        #pragma unroll
        for (int t = 0; t < NTAP; ++t) {
            const int dy = (t / 5) * 2, dx = (t % 5) * 2;
            unsigned long long ak = kS[t * 128 + pairG2];
            const float* px = pb + dy * PWP + dx;
            #pragma unroll
            for (int q = 0; q < 4; ++q) {
                unsigned long long xv =
                    *(const unsigned long long*)(px + q * (PH * PWP));
                accO[q] = ffma2(ak, xv, accO[q]);
            }
        }

        #pragma unroll
        for (int q = 0; q < 4; ++q) {
            float a, bv;
            unpack2(accO[q], a, bv);
            int ch = cc * CHK + chalf * 4 + q;
            *(float2*)&out[(((size_t)b * CCH + ch) * HH + (gy0 + prow)) * WW
                           + gx0 + pcol] = make_float2(a, bv);
        }
        __syncthreads();
    }
}

extern "C" void kernel_launch(void* const* d_in, const int* in_sizes, int n_in,
                              void* d_out, int out_size) {
    const float* x  = (const float*)d_in[0];
    const float* w1 = (const float*)d_in[1];
    const float* b1 = (const float*)d_in[2];
    const float* w2 = (const float*)d_in[3];
    const float* b2 = (const float*)d_in[4];
    float* out = (float*)d_out;

    k_precompute<<<(CCH * NTAP * NOUT + 255) / 256, 256>>>(w1, b1, w2, b2);

    cudaFuncSetAttribute(k_main, cudaFuncAttributeMaxDynamicSharedMemorySize, SM_TOTAL);

    dim3 grid(WW / TW, HH / TH, BB);   // 7 x 7 x 8 = 392 CTAs
    k_main<<<grid, NT, SM_TOTAL>>>(x, out);
}